// round 9
// baseline (speedup 1.0000x reference)
#include <cuda_runtime.h>

#define NN 50000
#define EE 300000
#define RR 4
#define FIN 11
#define HH 256
#define GG 2048
#define TT 19
#define RH 1024   // R*H
#define BN_EPS 1e-5f

// ---------------- scratch (device globals; no allocations allowed) ----------------
__device__ float g_B[(size_t)RR * NN * HH];       // per-relation (x + agg)
__device__ float g_Hcat[(size_t)NN * RH];         // [N, R*H] relation hidden states
__device__ float g_X0[(size_t)NN * HH];
__device__ float g_X1[(size_t)NN * HH];
__device__ float g_Wc[(size_t)(HH + RH) * HH];    // concat [sw; W2cat]
__device__ float g_sums[2 * RH];                  // col sums / sumsq
__device__ float g_scale[RH];
__device__ float g_shift[RH];
__device__ float g_bias0[HH];
__device__ float g_pool[GG * HH];
__device__ float g_cnt[GG];

// int32 copies of the index tensors (robust to harness int32-vs-int64)
__device__ int g_ei[2 * EE];
__device__ int g_et[EE];
__device__ int g_batch[NN];

// ---------------- index dtype sniff + convert ----------------
__global__ void convert_idx(const int* __restrict__ ei_raw,
                            const int* __restrict__ et_raw,
                            const int* __restrict__ b_raw) {
    bool is64 = (ei_raw[1] == 0 && ei_raw[3] == 0 && ei_raw[5] == 0 && ei_raw[7] == 0);
    int i = blockIdx.x * blockDim.x + threadIdx.x;
    int stride = gridDim.x * blockDim.x;
    for (int j = i; j < 2 * EE; j += stride) g_ei[j] = is64 ? ei_raw[2 * j] : ei_raw[j];
    for (int j = i; j < EE; j += stride)     g_et[j] = is64 ? et_raw[2 * j] : et_raw[j];
    for (int j = i; j < NN; j += stride)     g_batch[j] = is64 ? b_raw[2 * j] : b_raw[j];
}

// ---------------- helpers ----------------
__global__ void copyB_kernel(const float* __restrict__ X, int fin) {
    size_t per = (size_t)NN * fin / 4;
    size_t tot = per * RR;
    const float4* X4 = (const float4*)X;
    float4* B4 = (float4*)g_B;
    for (size_t i = (size_t)blockIdx.x * blockDim.x + threadIdx.x; i < tot;
         i += (size_t)gridDim.x * blockDim.x) {
        B4[i] = X4[i % per];
    }
}

// Scatter-add, fin==256: 64 threads/edge, float4 + vector red.
__global__ void scatter_f256_v4(const float* __restrict__ X) {
    int gid = blockIdx.x * blockDim.x + threadIdx.x;
    int e = gid >> 6;
    int q = gid & 63;
    if (e >= EE) return;
    int s = g_ei[e];
    int d = g_ei[EE + e];
    int r = g_et[e];
    float4 v = __ldg((const float4*)(X + (size_t)s * HH) + q);
    float* p = &g_B[((size_t)r * NN + d) * HH + q * 4];
    asm volatile("red.global.add.v4.f32 [%0], {%1,%2,%3,%4};"
                 :: "l"(p), "f"(v.x), "f"(v.y), "f"(v.z), "f"(v.w) : "memory");
}

// Scatter-add, fin==11 (layer 1)
__global__ void scatter_f11(const float* __restrict__ X) {
    int gid = blockIdx.x * blockDim.x + threadIdx.x;
    int e = gid >> 4;
    int k = gid & 15;
    if (e >= EE || k >= FIN) return;
    int s = g_ei[e];
    int d = g_ei[EE + e];
    int r = g_et[e];
    atomicAdd(&g_B[((size_t)r * NN + d) * FIN + k], X[(size_t)s * FIN + k]);
}

// concat W = [sw (fin rows) ; w2cat (RH rows)], all ld 256
__global__ void concatW(const float* __restrict__ sw, const float* __restrict__ w2, int fin) {
    int idx = blockIdx.x * blockDim.x + threadIdx.x;
    int tot = (fin + RH) * HH;
    if (idx >= tot) return;
    int k = idx >> 8;
    int c = idx & 255;
    g_Wc[idx] = (k < fin) ? sw[k * HH + c] : w2[(size_t)(k - fin) * HH + c];
}

// ---------------- tf32 tensor-core GEMM: 128x128 CTA tile, 8 warps @ 32x64 ----------------
// A = [A1 (K1 cols, lda=K1) | bn_relu(A2) (K2 cols, lda=RH)]
// C[row, bz*bsC+col] = A @ W  (+bias)(relu?) ; optional fused column stats -> g_sums
#define TBM 128
#define TBN 128
#define TBK 32

__device__ __forceinline__ unsigned f2tf(float v) {
    unsigned r;
    asm("cvt.rna.tf32.f32 %0, %1;" : "=r"(r) : "f"(v));
    return r;
}

__device__ __forceinline__ void mma8(float* c, const unsigned* a, const unsigned* b) {
    asm volatile(
        "mma.sync.aligned.m16n8k8.row.col.f32.tf32.tf32.f32 "
        "{%0,%1,%2,%3}, {%4,%5,%6,%7}, {%8,%9}, {%0,%1,%2,%3};"
        : "+f"(c[0]), "+f"(c[1]), "+f"(c[2]), "+f"(c[3])
        : "r"(a[0]), "r"(a[1]), "r"(a[2]), "r"(a[3]), "r"(b[0]), "r"(b[1]));
}

__global__ void __launch_bounds__(256)
tgemm(const float* __restrict__ A1, int K1, size_t bsA1,
      const float* __restrict__ A2, int K2, int bnA,
      int M,
      const float* __restrict__ W, size_t bsW,
      float* __restrict__ Cwr, int ldc, int bsC,
      const float* __restrict__ bias, int relu, int stats)
{
    int bz = blockIdx.z;
    A1 += (size_t)bz * bsA1;
    W += (size_t)bz * bsW;
    int Ktot = K1 + (A2 ? K2 : 0);

    int rowBase = blockIdx.y * TBM;
    int colTile = blockIdx.x * TBN;

    __shared__ unsigned As[TBM][36];   // As[m][k], pad 36 -> conflict-free
    __shared__ unsigned Bs[TBK][136];  // Bs[k][n]
    __shared__ float s_sum[TBN], s_sq[TBN];

    int tid = threadIdx.x;
    int lane = tid & 31;
    int warp = tid >> 5;
    int wr = (warp >> 1) * 32;
    int wc = (warp & 1) * 64;
    int gid = lane >> 2;
    int tq = lane & 3;

    float c[2][8][4];
#pragma unroll
    for (int i = 0; i < 2; i++)
#pragma unroll
        for (int j = 0; j < 8; j++)
#pragma unroll
            for (int q = 0; q < 4; q++) c[i][j][q] = 0.f;

    for (int k0 = 0; k0 < Ktot; k0 += TBK) {
        // ---- load A tile 128x32 with concat + optional BN+ReLU, convert to tf32 ----
        {
            int kq = (tid & 7) * 4;
            int rowq = tid >> 3;       // 0..31
#pragma unroll
            for (int p = 0; p < 4; p++) {
                int lr = rowq + p * 32;
                int row = rowBase + lr;
#pragma unroll
                for (int j = 0; j < 4; j++) {
                    int kk = k0 + kq + j;
                    float v = 0.f;
                    if (row < M && kk < Ktot) {
                        if (kk < K1) {
                            v = A1[(size_t)row * K1 + kk];
                        } else {
                            int k2 = kk - K1;
                            v = A2[(size_t)row * RH + k2];
                            if (bnA) v = fmaxf(fmaf(v, g_scale[k2], g_shift[k2]), 0.f);
                        }
                    }
                    As[lr][kq + j] = f2tf(v);
                }
            }
        }
        // ---- load W tile 32x128 (ldw = HH), convert to tf32 ----
        {
            int nq = (tid & 31) * 4;
            int kk0 = tid >> 5;        // 0..7
#pragma unroll
            for (int p = 0; p < 4; p++) {
                int lk = kk0 + p * 8;
                int kk = k0 + lk;
                const float* Wp = W + (size_t)kk * HH + colTile + nq;
#pragma unroll
                for (int j = 0; j < 4; j++) {
                    float v = (kk < Ktot) ? Wp[j] : 0.f;
                    Bs[lk][nq + j] = f2tf(v);
                }
            }
        }
        __syncthreads();

#pragma unroll
        for (int ks = 0; ks < 4; ks++) {
            int kb = ks * 8;
            unsigned a[2][4], b[8][2];
#pragma unroll
            for (int rb = 0; rb < 2; rb++) {
                int r = wr + rb * 16 + gid;
                a[rb][0] = As[r][kb + tq];
                a[rb][1] = As[r + 8][kb + tq];
                a[rb][2] = As[r][kb + tq + 4];
                a[rb][3] = As[r + 8][kb + tq + 4];
            }
#pragma unroll
            for (int cb = 0; cb < 8; cb++) {
                int cn = wc + cb * 8 + gid;
                b[cb][0] = Bs[kb + tq][cn];
                b[cb][1] = Bs[kb + tq + 4][cn];
            }
#pragma unroll
            for (int rb = 0; rb < 2; rb++)
#pragma unroll
                for (int cb = 0; cb < 8; cb++)
                    mma8(c[rb][cb], a[rb], b[cb]);
        }
        __syncthreads();
    }

    // ---- C write ----
#pragma unroll
    for (int rb = 0; rb < 2; rb++) {
        int r0 = rowBase + wr + rb * 16 + gid;
        int r1 = r0 + 8;
#pragma unroll
        for (int cb = 0; cb < 8; cb++) {
            int lcol = colTile + wc + cb * 8 + tq * 2;
#pragma unroll
            for (int j = 0; j < 2; j++) {
                int col = lcol + j;
                float bsum = bias ? bias[col] : 0.f;
                if (r0 < M) {
                    float v = c[rb][cb][j] + bsum;
                    if (relu) v = fmaxf(v, 0.f);
                    Cwr[(size_t)r0 * ldc + bz * bsC + col] = v;
                }
                if (r1 < M) {
                    float v = c[rb][cb][2 + j] + bsum;
                    if (relu) v = fmaxf(v, 0.f);
                    Cwr[(size_t)r1 * ldc + bz * bsC + col] = v;
                }
            }
        }
    }

    // ---- fused column stats (sum, sumsq) for BatchNorm ----
    if (stats) {
        if (tid < TBN) { s_sum[tid] = 0.f; s_sq[tid] = 0.f; }
        __syncthreads();
#pragma unroll
        for (int cb = 0; cb < 8; cb++) {
#pragma unroll
            for (int j = 0; j < 2; j++) {
                int lc = wc + cb * 8 + tq * 2 + j;
                float s = 0.f, q2 = 0.f;
#pragma unroll
                for (int rb = 0; rb < 2; rb++) {
                    int r0 = rowBase + wr + rb * 16 + gid;
                    if (r0 < M)     { float v = c[rb][cb][j];     s += v; q2 += v * v; }
                    if (r0 + 8 < M) { float v = c[rb][cb][2 + j]; s += v; q2 += v * v; }
                }
#pragma unroll
                for (int m = 4; m <= 16; m <<= 1) {
                    s  += __shfl_xor_sync(0xffffffffu, s, m);
                    q2 += __shfl_xor_sync(0xffffffffu, q2, m);
                }
                if (gid == 0) {
                    atomicAdd(&s_sum[lc], s);
                    atomicAdd(&s_sq[lc], q2);
                }
            }
        }
        __syncthreads();
        if (tid < TBN) {
            int scol = bz * bsC + colTile + tid;
            atomicAdd(&g_sums[scol], s_sum[tid]);
            atomicAdd(&g_sums[RH + scol], s_sq[tid]);
        }
    }
}

// ---------------- BatchNorm param finalize ----------------
__global__ void zero_stats() {
    int i = blockIdx.x * blockDim.x + threadIdx.x;
    if (i < 2 * RH) g_sums[i] = 0.f;
}

__global__ void bn_finalize(const float* __restrict__ g, const float* __restrict__ bt) {
    int c = blockIdx.x * blockDim.x + threadIdx.x;
    if (c < RH) {
        float mu  = g_sums[c] * (1.0f / NN);
        float var = g_sums[RH + c] * (1.0f / NN) - mu * mu;
        float sc  = g[c] * rsqrtf(var + BN_EPS);
        g_scale[c] = sc;
        g_shift[c] = bt[c] - mu * sc;
    }
}

// bias0 = sb + sum_r b2_r   (b1 cancels inside BN, so it's dropped)
__global__ void bias0_kernel(const float* __restrict__ sb, const float* __restrict__ b2) {
    int c = threadIdx.x;
    g_bias0[c] = sb[c] + b2[c] + b2[HH + c] + b2[2 * HH + c] + b2[3 * HH + c];
}

// ---------------- pooling + final linear ----------------
__global__ void pool_zero() {
    int i = blockIdx.x * blockDim.x + threadIdx.x;
    if (i < GG * HH) g_pool[i] = 0.f;
    if (i < GG) g_cnt[i] = 0.f;
}

__global__ void pool_scatter_v4(const float* __restrict__ X) {
    int gid = blockIdx.x * blockDim.x + threadIdx.x;
    int n = gid >> 6;
    int q = gid & 63;
    if (n >= NN) return;
    int b = g_batch[n];
    float4 v = __ldg((const float4*)(X + (size_t)n * HH) + q);
    float* p = &g_pool[b * HH + q * 4];
    asm volatile("red.global.add.v4.f32 [%0], {%1,%2,%3,%4};"
                 :: "l"(p), "f"(v.x), "f"(v.y), "f"(v.z), "f"(v.w) : "memory");
    if (q == 0) atomicAdd(&g_cnt[b], 1.f);
}

__global__ void final_linear(const float* __restrict__ lw, const float* __restrict__ lb,
                             float* __restrict__ out) {
    __shared__ float sh[HH];
    int g = blockIdx.x;
    float inv = 1.0f / fmaxf(g_cnt[g], 1.f);
    sh[threadIdx.x] = g_pool[g * HH + threadIdx.x] * inv;
    __syncthreads();
    if (threadIdx.x < TT) {
        int t = threadIdx.x;
        float acc = lb[t];
#pragma unroll 8
        for (int c = 0; c < HH; c++) acc += sh[c] * lw[c * TT + t];
        out[g * TT + t] = acc;
    }
}

// ---------------- orchestration ----------------
static void run_layer(const float* Xin, int fin,
                      const float* sw, const float* sb, const float* w1,
                      const float* gamma, const float* beta,
                      const float* w2, const float* b2,
                      float* pB, float* pHcat, float* pWc, float* pBias0,
                      float* Xout)
{
    // 1. B[r] = X; B[r][dst] += X[src] over edges of type r
    copyB_kernel<<<4096, 256>>>(Xin, fin);
    if (fin == HH) {
        scatter_f256_v4<<<(EE * 64) / 256, 256>>>(Xin);
    } else {
        scatter_f11<<<(EE * 16 + 255) / 256, 256>>>(Xin);
    }

    int mtiles = (NN + TBM - 1) / TBM;

    // 2. Hcat[:, r*H:(r+1)*H] = B[r] @ w1[r], with fused BN column stats
    zero_stats<<<2, 1024>>>();
    tgemm<<<dim3(HH / TBN, mtiles, RR), 256>>>(
        pB, fin, (size_t)NN * fin,
        nullptr, 0, 0,
        NN,
        w1, (size_t)fin * HH,
        pHcat, RH, HH, nullptr, 0, /*stats=*/1);

    // 3. BN scale/shift + fused biases + concat weights
    bn_finalize<<<4, 256>>>(gamma, beta);
    bias0_kernel<<<1, 256>>>(sb, b2);
    concatW<<<((fin + RH) * HH + 255) / 256, 256>>>(sw, w2, fin);

    // 4. Xout = relu( [Xin | bn_relu(Hcat)] @ [sw; W2cat] + bias0 )
    tgemm<<<dim3(HH / TBN, mtiles, 1), 256>>>(
        Xin, fin, 0,
        pHcat, RH, /*bnA=*/1,
        NN,
        pWc, 0,
        Xout, HH, 0, pBias0, /*relu=*/1, 0);
}

extern "C" void kernel_launch(void* const* d_in, const int* in_sizes, int n_in,
                              void* d_out, int out_size)
{
    const float* x     = (const float*)d_in[0];
    const int*   ei    = (const int*)d_in[1];   // int32 OR int64 raw words (sniffed)
    const int*   et    = (const int*)d_in[2];
    const int*   batch = (const int*)d_in[3];
    const float* lin_w = (const float*)d_in[28];
    const float* lin_b = (const float*)d_in[29];

    float *pB, *pHcat, *pX0, *pX1, *pWc, *pBias0;
    cudaGetSymbolAddress((void**)&pB, g_B);
    cudaGetSymbolAddress((void**)&pHcat, g_Hcat);
    cudaGetSymbolAddress((void**)&pX0, g_X0);
    cudaGetSymbolAddress((void**)&pX1, g_X1);
    cudaGetSymbolAddress((void**)&pWc, g_Wc);
    cudaGetSymbolAddress((void**)&pBias0, g_bias0);

    // normalize indices to int32 scratch (handles int32 or int64 inputs)
    convert_idx<<<1024, 256>>>(ei, et, batch);

    // layer params: base = 4 + 8*l : sw, sb, w1, b1(unused), g, bt, w2, b2
    const float* Xcur = x;
    float* outs[3] = {pX0, pX1, pX0};
    int fins[3] = {FIN, HH, HH};
    for (int l = 0; l < 3; l++) {
        int base = 4 + 8 * l;
        run_layer(Xcur, fins[l],
                  (const float*)d_in[base + 0], (const float*)d_in[base + 1],
                  (const float*)d_in[base + 2],
                  (const float*)d_in[base + 4], (const float*)d_in[base + 5],
                  (const float*)d_in[base + 6], (const float*)d_in[base + 7],
                  pB, pHcat, pWc, pBias0, outs[l]);
        Xcur = outs[l];
    }

    // global mean pool + final linear
    pool_zero<<<(GG * HH + 255) / 256, 256>>>();
    pool_scatter_v4<<<(NN * 64 + 255) / 256, 256>>>(Xcur);
    final_linear<<<GG, HH>>>(lin_w, lin_b, (float*)d_out);
}

// round 10
// speedup vs baseline: 2.6448x; 2.6448x over previous
#include <cuda_runtime.h>

#define NN 50000
#define EE 300000
#define RR 4
#define FIN 11
#define HH 256
#define GG 2048
#define TT 19
#define RH 1024   // R*H
#define BN_EPS 1e-5f

// ---------------- scratch (device globals; no allocations allowed) ----------------
__device__ float g_B[(size_t)RR * NN * HH];       // per-relation (x + agg)
__device__ float g_Hcat[(size_t)NN * RH];         // [N, R*H] relation hidden states
__device__ float g_X0[(size_t)NN * HH];
__device__ float g_X1[(size_t)NN * HH];
__device__ float g_Wc[(size_t)(HH + RH) * HH];    // concat [sw; pad; W2cat]
__device__ float g_sums[2 * RH];                  // col sums / sumsq
__device__ float g_scale[RH];
__device__ float g_shift[RH];
__device__ float g_bias0[HH];
__device__ float g_pool[GG * HH];
__device__ float g_cnt[GG];

// int32 copies of the index tensors (robust to harness int32-vs-int64)
__device__ int g_ei[2 * EE];
__device__ int g_et[EE];
__device__ int g_batch[NN];

// ---------------- index dtype sniff + convert ----------------
__global__ void convert_idx(const int* __restrict__ ei_raw,
                            const int* __restrict__ et_raw,
                            const int* __restrict__ b_raw) {
    bool is64 = (ei_raw[1] == 0 && ei_raw[3] == 0 && ei_raw[5] == 0 && ei_raw[7] == 0);
    int i = blockIdx.x * blockDim.x + threadIdx.x;
    int stride = gridDim.x * blockDim.x;
    for (int j = i; j < 2 * EE; j += stride) g_ei[j] = is64 ? ei_raw[2 * j] : ei_raw[j];
    for (int j = i; j < EE; j += stride)     g_et[j] = is64 ? et_raw[2 * j] : et_raw[j];
    for (int j = i; j < NN; j += stride)     g_batch[j] = is64 ? b_raw[2 * j] : b_raw[j];
}

// ---------------- helpers ----------------
__global__ void copyB_kernel(const float* __restrict__ X, int fin) {
    size_t per = (size_t)NN * fin / 4;
    size_t tot = per * RR;
    const float4* X4 = (const float4*)X;
    float4* B4 = (float4*)g_B;
    for (size_t i = (size_t)blockIdx.x * blockDim.x + threadIdx.x; i < tot;
         i += (size_t)gridDim.x * blockDim.x) {
        B4[i] = X4[i % per];
    }
}

// Scatter-add, fin==256: 64 threads/edge, float4 + vector red.
__global__ void scatter_f256_v4(const float* __restrict__ X) {
    int gid = blockIdx.x * blockDim.x + threadIdx.x;
    int e = gid >> 6;
    int q = gid & 63;
    if (e >= EE) return;
    int s = g_ei[e];
    int d = g_ei[EE + e];
    int r = g_et[e];
    float4 v = __ldg((const float4*)(X + (size_t)s * HH) + q);
    float* p = &g_B[((size_t)r * NN + d) * HH + q * 4];
    asm volatile("red.global.add.v4.f32 [%0], {%1,%2,%3,%4};"
                 :: "l"(p), "f"(v.x), "f"(v.y), "f"(v.z), "f"(v.w) : "memory");
}

// Scatter-add, fin==11 (layer 1)
__global__ void scatter_f11(const float* __restrict__ X) {
    int gid = blockIdx.x * blockDim.x + threadIdx.x;
    int e = gid >> 4;
    int k = gid & 15;
    if (e >= EE || k >= FIN) return;
    int s = g_ei[e];
    int d = g_ei[EE + e];
    int r = g_et[e];
    atomicAdd(&g_B[((size_t)r * NN + d) * FIN + k], X[(size_t)s * FIN + k]);
}

// concat W = [sw (fin rows); zeros (K1pad-fin rows); w2cat (RH rows)], ld 256
__global__ void concatW(const float* __restrict__ sw, const float* __restrict__ w2,
                        int fin, int k1pad) {
    int idx = blockIdx.x * blockDim.x + threadIdx.x;
    int tot = (k1pad + RH) * HH;
    if (idx >= tot) return;
    int k = idx >> 8;
    int c = idx & 255;
    float v = 0.f;
    if (k < fin)            v = sw[k * HH + c];
    else if (k >= k1pad)    v = w2[(size_t)(k - k1pad) * HH + c];
    g_Wc[idx] = v;
}

// ---------------- tf32 tensor-core GEMM: 128x128 CTA tile, 8 warps @ 32x64 ----------------
// A = [A1 (K1 real cols padded to K1pad, lda=K1) | bn_relu(A2) (RH cols, lda=RH)]
// C[row, bz*bsC+col] = A @ W (+bias)(relu?) ; optional fused column stats -> g_sums
// Region boundary K1pad is a multiple of TBK, so each k-tile is wholly in one region.
#define TBM 128
#define TBN 128
#define TBK 32

__device__ __forceinline__ unsigned f2tf(float v) {
    unsigned r;
    asm("cvt.rna.tf32.f32 %0, %1;" : "=r"(r) : "f"(v));
    return r;
}

__device__ __forceinline__ void mma8(float* c, const unsigned* a, const unsigned* b) {
    asm volatile(
        "mma.sync.aligned.m16n8k8.row.col.f32.tf32.tf32.f32 "
        "{%0,%1,%2,%3}, {%4,%5,%6,%7}, {%8,%9}, {%0,%1,%2,%3};"
        : "+f"(c[0]), "+f"(c[1]), "+f"(c[2]), "+f"(c[3])
        : "r"(a[0]), "r"(a[1]), "r"(a[2]), "r"(a[3]), "r"(b[0]), "r"(b[1]));
}

__global__ void __launch_bounds__(256)
tgemm(const float* __restrict__ A1, int K1, int K1pad, size_t bsA1,
      const float* __restrict__ A2,
      int M,
      const float* __restrict__ W, int KW, size_t bsW,
      float* __restrict__ Cwr, int ldc, int bsC,
      const float* __restrict__ bias, int relu, int stats)
{
    int bz = blockIdx.z;
    A1 += (size_t)bz * bsA1;
    W += (size_t)bz * bsW;
    int Ktot = K1pad + (A2 ? RH : 0);

    int rowBase = blockIdx.y * TBM;
    int colTile = blockIdx.x * TBN;

    __shared__ unsigned As[TBM][36];   // As[m][k], pad 36 -> conflict-free
    __shared__ unsigned Bs[TBK][136];  // Bs[k][n]
    __shared__ float s_sum[TBN], s_sq[TBN];

    int tid = threadIdx.x;
    int lane = tid & 31;
    int warp = tid >> 5;
    int wr = (warp >> 1) * 32;
    int wc = (warp & 1) * 64;
    int gid = lane >> 2;
    int tq = lane & 3;

    float c[2][8][4];
#pragma unroll
    for (int i = 0; i < 2; i++)
#pragma unroll
        for (int j = 0; j < 8; j++)
#pragma unroll
            for (int q = 0; q < 4; q++) c[i][j][q] = 0.f;

    int kqA = (tid & 7) * 4;       // 0..28, fixed per thread
    int rowqA = tid >> 3;          // 0..31

    for (int k0 = 0; k0 < Ktot; k0 += TBK) {
        // ---- A tile 128x32, tile-uniform region select ----
        if (k0 < K1pad) {
            if (K1 == K1pad) {
                // full-width region 1 (fin==256): vector loads
#pragma unroll
                for (int p = 0; p < 4; p++) {
                    int lr = rowqA + p * 32;
                    int row = rowBase + lr;
                    float4 v = make_float4(0.f, 0.f, 0.f, 0.f);
                    if (row < M) v = *(const float4*)(A1 + (size_t)row * K1 + k0 + kqA);
                    As[lr][kqA + 0] = f2tf(v.x);
                    As[lr][kqA + 1] = f2tf(v.y);
                    As[lr][kqA + 2] = f2tf(v.z);
                    As[lr][kqA + 3] = f2tf(v.w);
                }
            } else {
                // padded region 1 (fin==11): scalar guarded, only 1 tile
#pragma unroll
                for (int p = 0; p < 4; p++) {
                    int lr = rowqA + p * 32;
                    int row = rowBase + lr;
#pragma unroll
                    for (int j = 0; j < 4; j++) {
                        int kk = k0 + kqA + j;
                        float v = 0.f;
                        if (row < M && kk < K1) v = A1[(size_t)row * K1 + kk];
                        As[lr][kqA + j] = f2tf(v);
                    }
                }
            }
        } else {
            // region 2: Hcat with BN+ReLU; scale/shift via 2 float4 loads per tile
            int k2 = k0 - K1pad + kqA;
            float4 sc4 = *(const float4*)(g_scale + k2);
            float4 sh4 = *(const float4*)(g_shift + k2);
#pragma unroll
            for (int p = 0; p < 4; p++) {
                int lr = rowqA + p * 32;
                int row = rowBase + lr;
                float4 v = make_float4(0.f, 0.f, 0.f, 0.f);
                if (row < M) v = *(const float4*)(A2 + (size_t)row * RH + k2);
                As[lr][kqA + 0] = f2tf(fmaxf(fmaf(v.x, sc4.x, sh4.x), 0.f));
                As[lr][kqA + 1] = f2tf(fmaxf(fmaf(v.y, sc4.y, sh4.y), 0.f));
                As[lr][kqA + 2] = f2tf(fmaxf(fmaf(v.z, sc4.z, sh4.z), 0.f));
                As[lr][kqA + 3] = f2tf(fmaxf(fmaf(v.w, sc4.w, sh4.w), 0.f));
            }
        }
        // ---- W tile 32x128 (ldw = HH), vector loads ----
        {
            int nq = (tid & 31) * 4;
            int kk0 = tid >> 5;        // 0..7
#pragma unroll
            for (int p = 0; p < 4; p++) {
                int lk = kk0 + p * 8;
                int kk = k0 + lk;
                float4 v = make_float4(0.f, 0.f, 0.f, 0.f);
                if (kk < KW) v = *(const float4*)(W + (size_t)kk * HH + colTile + nq);
                Bs[lk][nq + 0] = f2tf(v.x);
                Bs[lk][nq + 1] = f2tf(v.y);
                Bs[lk][nq + 2] = f2tf(v.z);
                Bs[lk][nq + 3] = f2tf(v.w);
            }
        }
        __syncthreads();

#pragma unroll
        for (int ks = 0; ks < 4; ks++) {
            int kb = ks * 8;
            unsigned a[2][4], b[8][2];
#pragma unroll
            for (int rb = 0; rb < 2; rb++) {
                int r = wr + rb * 16 + gid;
                a[rb][0] = As[r][kb + tq];
                a[rb][1] = As[r + 8][kb + tq];
                a[rb][2] = As[r][kb + tq + 4];
                a[rb][3] = As[r + 8][kb + tq + 4];
            }
#pragma unroll
            for (int cb = 0; cb < 8; cb++) {
                int cn = wc + cb * 8 + gid;
                b[cb][0] = Bs[kb + tq][cn];
                b[cb][1] = Bs[kb + tq + 4][cn];
            }
#pragma unroll
            for (int rb = 0; rb < 2; rb++)
#pragma unroll
                for (int cb = 0; cb < 8; cb++)
                    mma8(c[rb][cb], a[rb], b[cb]);
        }
        __syncthreads();
    }

    // ---- C write ----
#pragma unroll
    for (int rb = 0; rb < 2; rb++) {
        int r0 = rowBase + wr + rb * 16 + gid;
        int r1 = r0 + 8;
#pragma unroll
        for (int cb = 0; cb < 8; cb++) {
            int lcol = colTile + wc + cb * 8 + tq * 2;
#pragma unroll
            for (int j = 0; j < 2; j++) {
                int col = lcol + j;
                float bsum = bias ? bias[col] : 0.f;
                if (r0 < M) {
                    float v = c[rb][cb][j] + bsum;
                    if (relu) v = fmaxf(v, 0.f);
                    Cwr[(size_t)r0 * ldc + bz * bsC + col] = v;
                }
                if (r1 < M) {
                    float v = c[rb][cb][2 + j] + bsum;
                    if (relu) v = fmaxf(v, 0.f);
                    Cwr[(size_t)r1 * ldc + bz * bsC + col] = v;
                }
            }
        }
    }

    // ---- fused column stats (sum, sumsq) for BatchNorm ----
    if (stats) {
        if (tid < TBN) { s_sum[tid] = 0.f; s_sq[tid] = 0.f; }
        __syncthreads();
#pragma unroll
        for (int cb = 0; cb < 8; cb++) {
#pragma unroll
            for (int j = 0; j < 2; j++) {
                int lc = wc + cb * 8 + tq * 2 + j;
                float s = 0.f, q2 = 0.f;
#pragma unroll
                for (int rb = 0; rb < 2; rb++) {
                    int r0 = rowBase + wr + rb * 16 + gid;
                    if (r0 < M)     { float v = c[rb][cb][j];     s += v; q2 += v * v; }
                    if (r0 + 8 < M) { float v = c[rb][cb][2 + j]; s += v; q2 += v * v; }
                }
#pragma unroll
                for (int m = 4; m <= 16; m <<= 1) {
                    s  += __shfl_xor_sync(0xffffffffu, s, m);
                    q2 += __shfl_xor_sync(0xffffffffu, q2, m);
                }
                if (gid == 0) {
                    atomicAdd(&s_sum[lc], s);
                    atomicAdd(&s_sq[lc], q2);
                }
            }
        }
        __syncthreads();
        if (tid < TBN) {
            int scol = bz * bsC + colTile + tid;
            atomicAdd(&g_sums[scol], s_sum[tid]);
            atomicAdd(&g_sums[RH + scol], s_sq[tid]);
        }
    }
}

// ---------------- BatchNorm param finalize ----------------
__global__ void zero_stats() {
    int i = blockIdx.x * blockDim.x + threadIdx.x;
    if (i < 2 * RH) g_sums[i] = 0.f;
}

__global__ void bn_finalize(const float* __restrict__ g, const float* __restrict__ bt) {
    int c = blockIdx.x * blockDim.x + threadIdx.x;
    if (c < RH) {
        float mu  = g_sums[c] * (1.0f / NN);
        float var = g_sums[RH + c] * (1.0f / NN) - mu * mu;
        float sc  = g[c] * rsqrtf(var + BN_EPS);
        g_scale[c] = sc;
        g_shift[c] = bt[c] - mu * sc;
    }
}

// bias0 = sb + sum_r b2_r   (b1 cancels inside BN, so it's dropped)
__global__ void bias0_kernel(const float* __restrict__ sb, const float* __restrict__ b2) {
    int c = threadIdx.x;
    g_bias0[c] = sb[c] + b2[c] + b2[HH + c] + b2[2 * HH + c] + b2[3 * HH + c];
}

// ---------------- pooling + final linear ----------------
__global__ void pool_zero() {
    int i = blockIdx.x * blockDim.x + threadIdx.x;
    if (i < GG * HH) g_pool[i] = 0.f;
    if (i < GG) g_cnt[i] = 0.f;
}

__global__ void pool_scatter_v4(const float* __restrict__ X) {
    int gid = blockIdx.x * blockDim.x + threadIdx.x;
    int n = gid >> 6;
    int q = gid & 63;
    if (n >= NN) return;
    int b = g_batch[n];
    float4 v = __ldg((const float4*)(X + (size_t)n * HH) + q);
    float* p = &g_pool[b * HH + q * 4];
    asm volatile("red.global.add.v4.f32 [%0], {%1,%2,%3,%4};"
                 :: "l"(p), "f"(v.x), "f"(v.y), "f"(v.z), "f"(v.w) : "memory");
    if (q == 0) atomicAdd(&g_cnt[b], 1.f);
}

__global__ void final_linear(const float* __restrict__ lw, const float* __restrict__ lb,
                             float* __restrict__ out) {
    __shared__ float sh[HH];
    int g = blockIdx.x;
    float inv = 1.0f / fmaxf(g_cnt[g], 1.f);
    sh[threadIdx.x] = g_pool[g * HH + threadIdx.x] * inv;
    __syncthreads();
    if (threadIdx.x < TT) {
        int t = threadIdx.x;
        float acc = lb[t];
#pragma unroll 8
        for (int c = 0; c < HH; c++) acc += sh[c] * lw[c * TT + t];
        out[g * TT + t] = acc;
    }
}

// ---------------- orchestration ----------------
static void run_layer(const float* Xin, int fin,
                      const float* sw, const float* sb, const float* w1,
                      const float* gamma, const float* beta,
                      const float* w2, const float* b2,
                      float* pB, float* pHcat, float* pWc, float* pBias0,
                      float* Xout)
{
    int k1pad = (fin == FIN) ? 32 : HH;   // multiple of TBK

    // 1. B[r] = X; B[r][dst] += X[src] over edges of type r
    copyB_kernel<<<4096, 256>>>(Xin, fin);
    if (fin == HH) {
        scatter_f256_v4<<<(EE * 64) / 256, 256>>>(Xin);
    } else {
        scatter_f11<<<(EE * 16 + 255) / 256, 256>>>(Xin);
    }

    int mtiles = (NN + TBM - 1) / TBM;

    // 2. Hcat[:, r*H:(r+1)*H] = B[r] @ w1[r], with fused BN column stats
    zero_stats<<<2, 1024>>>();
    tgemm<<<dim3(HH / TBN, mtiles, RR), 256>>>(
        pB, fin, (fin == FIN) ? 32 : fin, (size_t)NN * fin,
        nullptr,
        NN,
        w1, fin, (size_t)fin * HH,
        pHcat, RH, HH, nullptr, 0, /*stats=*/1);

    // 3. BN scale/shift + fused biases + concat weights [sw; pad; W2cat]
    bn_finalize<<<4, 256>>>(gamma, beta);
    bias0_kernel<<<1, 256>>>(sb, b2);
    concatW<<<((k1pad + RH) * HH + 255) / 256, 256>>>(sw, w2, fin, k1pad);

    // 4. Xout = relu( [Xin|pad | bn_relu(Hcat)] @ Wc + bias0 )
    tgemm<<<dim3(HH / TBN, mtiles, 1), 256>>>(
        Xin, fin, k1pad, 0,
        pHcat,
        NN,
        pWc, k1pad + RH, 0,
        Xout, HH, 0, pBias0, /*relu=*/1, 0);
}

extern "C" void kernel_launch(void* const* d_in, const int* in_sizes, int n_in,
                              void* d_out, int out_size)
{
    const float* x     = (const float*)d_in[0];
    const int*   ei    = (const int*)d_in[1];   // int32 OR int64 raw words (sniffed)
    const int*   et    = (const int*)d_in[2];
    const int*   batch = (const int*)d_in[3];
    const float* lin_w = (const float*)d_in[28];
    const float* lin_b = (const float*)d_in[29];

    float *pB, *pHcat, *pX0, *pX1, *pWc, *pBias0;
    cudaGetSymbolAddress((void**)&pB, g_B);
    cudaGetSymbolAddress((void**)&pHcat, g_Hcat);
    cudaGetSymbolAddress((void**)&pX0, g_X0);
    cudaGetSymbolAddress((void**)&pX1, g_X1);
    cudaGetSymbolAddress((void**)&pWc, g_Wc);
    cudaGetSymbolAddress((void**)&pBias0, g_bias0);

    // normalize indices to int32 scratch (handles int32 or int64 inputs)
    convert_idx<<<1024, 256>>>(ei, et, batch);

    // layer params: base = 4 + 8*l : sw, sb, w1, b1(unused), g, bt, w2, b2
    const float* Xcur = x;
    float* outs[3] = {pX0, pX1, pX0};
    int fins[3] = {FIN, HH, HH};
    for (int l = 0; l < 3; l++) {
        int base = 4 + 8 * l;
        run_layer(Xcur, fins[l],
                  (const float*)d_in[base + 0], (const float*)d_in[base + 1],
                  (const float*)d_in[base + 2],
                  (const float*)d_in[base + 4], (const float*)d_in[base + 5],
                  (const float*)d_in[base + 6], (const float*)d_in[base + 7],
                  pB, pHcat, pWc, pBias0, outs[l]);
        Xcur = outs[l];
    }

    // global mean pool + final linear
    pool_zero<<<(GG * HH + 255) / 256, 256>>>();
    pool_scatter_v4<<<(NN * 64 + 255) / 256, 256>>>(Xcur);
    final_linear<<<GG, HH>>>(lin_w, lin_b, (float*)d_out);
}